// round 14
// baseline (speedup 1.0000x reference)
#include <cuda_runtime.h>
#include <cuda_fp16.h>
#include <cstdint>

#define N_NODES 100000
#define N_EDGES 1600000
#define NGRAPH  512
#define VOCAB   10000
#define D0 64
#define D1 128
#define SCAN_NB 391   // ceil(N_NODES / 256)

// ---------------- scratch (device globals) ----------------
__device__ int g_cnt[N_NODES];
__device__ int g_rowptr[N_NODES + 1];
__device__ int g_cur[N_NODES];
__device__ int g_bsum[SCAN_NB];
__device__ int g_boff[SCAN_NB];
__device__ __align__(8) int2 g_nbr2[N_EDGES];        // {src node id, x[src]} per CSR slot

__device__ __align__(16) __half g_q[VOCAB * D1];     // embed @ W1l   (fp16, 2.56MB)
__device__ __align__(16) float  g_R[VOCAB * D1];     // embed @ W1r   (fp32, 5.12MB)
__device__ __align__(16) __half g_h1h[N_NODES * D1]; // relu layer1   (fp16, 25.6MB)
__device__ __align__(16) __half g_p[N_NODES * D0];   // h1 @ W2l      (fp16, 12.8MB)
__device__ __align__(16) float  g_r[N_NODES * D0];   // h1 @ W2r      (25.6MB)
__device__ __align__(16) float  g_agg2[N_NODES * D0];
__device__ unsigned g_omax[NGRAPH * D0];

// ordered-uint mapping: monotone in float value
__device__ __forceinline__ unsigned ordf(float f) {
    unsigned u = __float_as_uint(f);
    return (u & 0x80000000u) ? ~u : (u | 0x80000000u);
}
#define ORD_NEG_INIT 0x00800000u   // ordf(-FLT_MAX)

// ---------------- f32x2 packed math ----------------
__device__ __forceinline__ unsigned long long pk2(float x, float y) {
    unsigned long long r;
    asm("mov.b64 %0, {%1, %2};" : "=l"(r) : "f"(x), "f"(y));
    return r;
}
__device__ __forceinline__ float2 upk2(unsigned long long v) {
    float2 r;
    asm("mov.b64 {%0, %1}, %2;" : "=f"(r.x), "=f"(r.y) : "l"(v));
    return r;
}
__device__ __forceinline__ void ffma2(unsigned long long& d, unsigned long long a,
                                      unsigned long long b) {
    asm("fma.rn.f32x2 %0, %1, %2, %0;" : "+l"(d) : "l"(a), "l"(b));
}

// ---------------- zinit: zero counters, arm omax (main stream head) ----------------
__global__ void zinit_kernel() {
    int gid = blockIdx.x * 256 + threadIdx.x;
    int stride = gridDim.x * 256;
    for (int j = gid; j < N_NODES; j += stride) g_cnt[j] = 0;
    for (int j = gid; j < NGRAPH * D0; j += stride) g_omax[j] = ORD_NEG_INIT;
}

// ---------------- preQR: Q = embed@W1l (fp16), R = embed@W1r (fp32) [stream B] -----
__global__ void preqr_kernel(const float* __restrict__ embed,
                             const float* __restrict__ W1l,
                             const float* __restrict__ W1r) {
    int gid = blockIdx.x * 256 + threadIdx.x;
    if (gid >= VOCAB * D1) return;
    int v = gid >> 7, c = gid & 127;
    float q = 0.f, r = 0.f;
#pragma unroll 8
    for (int k = 0; k < 64; k++) {
        float e = __ldg(embed + v * 64 + k);
        q = fmaf(e, __ldg(W1l + k * 128 + c), q);
        r = fmaf(e, __ldg(W1r + k * 128 + c), r);
    }
    g_q[gid] = __float2half_rn(q);
    g_R[gid] = r;
}

// ---------------- histogram of dst ----------------
__global__ void hist_kernel(const int* __restrict__ dst) {
    int e = blockIdx.x * 256 + threadIdx.x;
    if (e < N_EDGES) atomicAdd(&g_cnt[dst[e]], 1);
}

// ---------------- scan step 1 ----------------
__global__ void scan1_kernel() {
    int b = blockIdx.x;
    int i = b * 256 + threadIdx.x;
    int v = (i < N_NODES) ? g_cnt[i] : 0;
#pragma unroll
    for (int o = 16; o; o >>= 1) v += __shfl_down_sync(0xFFFFFFFFu, v, o);
    __shared__ int ws[8];
    if ((threadIdx.x & 31) == 0) ws[threadIdx.x >> 5] = v;
    __syncthreads();
    if (threadIdx.x == 0) {
        int s = 0;
#pragma unroll
        for (int k = 0; k < 8; k++) s += ws[k];
        g_bsum[b] = s;
    }
}

// ---------------- scan step 2 ----------------
__global__ void scan2_kernel() {
    __shared__ int s[512];
    int t = threadIdx.x;
    int v = (t < SCAN_NB) ? g_bsum[t] : 0;
    s[t] = v;
    __syncthreads();
    for (int o = 1; o < 512; o <<= 1) {
        int u = (t >= o) ? s[t - o] : 0;
        __syncthreads();
        s[t] += u;
        __syncthreads();
    }
    if (t < SCAN_NB) g_boff[t] = s[t] - v;
    if (t == 0) g_rowptr[N_NODES] = N_EDGES;
}

// ---------------- scan step 3 ----------------
__global__ void scan3_kernel() {
    int b = blockIdx.x, t = threadIdx.x;
    int i = b * 256 + t;
    int v = (i < N_NODES) ? g_cnt[i] : 0;
    int lane = t & 31, w = t >> 5;
    int sc = v;
#pragma unroll
    for (int o = 1; o < 32; o <<= 1) {
        int u = __shfl_up_sync(0xFFFFFFFFu, sc, o);
        if (lane >= o) sc += u;
    }
    __shared__ int ws[8];
    if (lane == 31) ws[w] = sc;
    __syncthreads();
    if (t < 8) {
        int u = ws[t];
        int s2 = u;
#pragma unroll
        for (int o = 1; o < 8; o <<= 1) {
            int q = __shfl_up_sync(0xFFu, s2, o);
            if (t >= o) s2 += q;
        }
        ws[t] = s2 - u;
    }
    __syncthreads();
    int excl = sc - v + ws[w] + g_boff[b];
    if (i < N_NODES) {
        g_rowptr[i] = excl;
        g_cur[i] = excl;
    }
}

// ---------------- fill neighbor lists: single int2 {src, x[src]} store -------------
__global__ void fill_kernel(const int* __restrict__ src, const int* __restrict__ dst,
                            const int* __restrict__ x) {
    int e = blockIdx.x * 256 + threadIdx.x;
    if (e >= N_EDGES) return;
    int d = dst[e];
    int s = src[e];
    int xs = __ldg(x + s);
    int pos = atomicAdd(&g_cur[d], 1);
    g_nbr2[pos] = make_int2(s, xs);
}

// ---------------- gather1h (chunked): h1[n] = relu(mean Q[x[s]] + R[x[n]] + b1) -----
// warp per node; lane covers 4 cols (uint2 = 4 halves). 8-edge unroll for MLP.
__global__ void __launch_bounds__(256) gather1h_kernel(const int* __restrict__ x,
                                                       const float* __restrict__ b1,
                                                       int n_base) {
    int gt = blockIdx.x * 256 + threadIdx.x;
    int n = n_base + (gt >> 5);
    if (n >= N_NODES) return;
    int lane = gt & 31;
    int beg = __ldg(g_rowptr + n), end = __ldg(g_rowptr + n + 1);
    const uint2* q2 = (const uint2*)g_q;   // row stride 32 uint2

    float a0 = 0.f, a1 = 0.f, a2 = 0.f, a3 = 0.f;
#define ACC4(U) do { \
    float2 f0 = __half22float2(*(const __half2*)&(U).x); \
    float2 f1 = __half22float2(*(const __half2*)&(U).y); \
    a0 += f0.x; a1 += f0.y; a2 += f1.x; a3 += f1.y; } while (0)
    int j = beg;
    for (; j + 7 < end; j += 8) {
        uint2 u0 = __ldg(q2 + __ldg(&g_nbr2[j].y)     * 32 + lane);
        uint2 u1 = __ldg(q2 + __ldg(&g_nbr2[j + 1].y) * 32 + lane);
        uint2 u2 = __ldg(q2 + __ldg(&g_nbr2[j + 2].y) * 32 + lane);
        uint2 u3 = __ldg(q2 + __ldg(&g_nbr2[j + 3].y) * 32 + lane);
        uint2 u4 = __ldg(q2 + __ldg(&g_nbr2[j + 4].y) * 32 + lane);
        uint2 u5 = __ldg(q2 + __ldg(&g_nbr2[j + 5].y) * 32 + lane);
        uint2 u6 = __ldg(q2 + __ldg(&g_nbr2[j + 6].y) * 32 + lane);
        uint2 u7 = __ldg(q2 + __ldg(&g_nbr2[j + 7].y) * 32 + lane);
        ACC4(u0); ACC4(u1); ACC4(u2); ACC4(u3);
        ACC4(u4); ACC4(u5); ACC4(u6); ACC4(u7);
    }
    for (; j + 3 < end; j += 4) {
        uint2 u0 = __ldg(q2 + __ldg(&g_nbr2[j].y)     * 32 + lane);
        uint2 u1 = __ldg(q2 + __ldg(&g_nbr2[j + 1].y) * 32 + lane);
        uint2 u2 = __ldg(q2 + __ldg(&g_nbr2[j + 2].y) * 32 + lane);
        uint2 u3 = __ldg(q2 + __ldg(&g_nbr2[j + 3].y) * 32 + lane);
        ACC4(u0); ACC4(u1); ACC4(u2); ACC4(u3);
    }
    for (; j < end; j++) {
        uint2 u0 = __ldg(q2 + __ldg(&g_nbr2[j].y) * 32 + lane);
        ACC4(u0);
    }
#undef ACC4
    float inv = 1.0f / fmaxf((float)(end - beg), 1.0f);
    int xn = __ldg(x + n);
    float4 rv = __ldg(((const float4*)g_R) + xn * 32 + lane);
    float4 bv = __ldg(((const float4*)b1) + lane);
    __half2 h01 = __floats2half2_rn(fmaxf(fmaf(a0, inv, rv.x + bv.x), 0.f),
                                    fmaxf(fmaf(a1, inv, rv.y + bv.y), 0.f));
    __half2 h23 = __floats2half2_rn(fmaxf(fmaf(a2, inv, rv.z + bv.z), 0.f),
                                    fmaxf(fmaf(a3, inv, rv.w + bv.w), 0.f));
    uint2 o;
    o.x = *(const unsigned*)&h01;
    o.y = *(const unsigned*)&h23;
    ((uint2*)g_h1h)[n * 32 + lane] = o;
}

// ---------------- dense2 (chunked): [p | r] = h1 @ [W2l | W2r]  via f32x2 ----------
__global__ void __launch_bounds__(256) dense2_kernel(const float* __restrict__ W2l,
                                                     const float* __restrict__ W2r,
                                                     int tile_base) {
    extern __shared__ float sm[];
    float* sW = sm;            // 16384 floats: [(k>>1)*256 + c*2 + (k&1)]
    float* sH = sm + 16384;    // 8192 floats:  [(t>>1)*256 + (k>>1)*4 + (t&1)*2 + (k&1)]
    const int tid = threadIdx.x, lane = tid & 31, wid = tid >> 5;
    const int n0 = (tile_base + blockIdx.x) * 64;

    for (int idx = tid; idx < 16384; idx += 256) {
        int k = idx >> 7, c = idx & 127;
        float v = (c < 64) ? __ldg(W2l + k * 64 + c) : __ldg(W2r + k * 64 + (c - 64));
        sW[((k >> 1) << 8) + (c << 1) + (k & 1)] = v;
    }
    // stage h1 tile from fp16: each idx covers (t, 4 consecutive k)
    for (int idx = tid; idx < 2048; idx += 256) {
        int t = idx >> 5, kq = idx & 31;     // kq: group of 4 k
        int n = n0 + t;
        uint2 u = (n < N_NODES) ? __ldg(((const uint2*)g_h1h) + n * 32 + kq)
                                : make_uint2(0u, 0u);
        float2 f0 = __half22float2(*(const __half2*)&u.x);
        float2 f1 = __half22float2(*(const __half2*)&u.y);
        float* dstp = sH + ((t >> 1) << 8) + (kq << 3) + ((t & 1) << 1);
        *(float2*)dstp = f0;
        *(float2*)(dstp + 4) = f1;
    }
    __syncthreads();

    const int ng = (wid & 3) * 16;      // node group base (16 nodes)
    const int ch = (wid >> 2) * 64;     // col half: 0 -> p, 64 -> r
    unsigned long long acc[16][2];
#pragma unroll
    for (int nn = 0; nn < 16; nn++) { acc[nn][0] = 0ull; acc[nn][1] = 0ull; }

    const float2* sW2 = (const float2*)sW;   // float2 idx = j2*128 + c
    const float4* sH4 = (const float4*)sH;   // float4 idx = (t>>1)*64 + j2

    for (int j2 = 0; j2 < 64; j2++) {
        float2 t0 = sW2[j2 * 128 + ch + lane];
        float2 t1 = sW2[j2 * 128 + ch + lane + 32];
        unsigned long long w0 = pk2(t0.x, t0.y);
        unsigned long long w1 = pk2(t1.x, t1.y);
#pragma unroll
        for (int p8 = 0; p8 < 8; p8++) {
            float4 hv = sH4[((ng >> 1) + p8) * 64 + j2];   // broadcast
            unsigned long long h0 = pk2(hv.x, hv.y);
            unsigned long long h1v = pk2(hv.z, hv.w);
            ffma2(acc[2 * p8][0], h0, w0);
            ffma2(acc[2 * p8][1], h0, w1);
            ffma2(acc[2 * p8 + 1][0], h1v, w0);
            ffma2(acc[2 * p8 + 1][1], h1v, w1);
        }
    }

#pragma unroll
    for (int nn = 0; nn < 16; nn++) {
        int node = n0 + ng + nn;
        if (node >= N_NODES) break;
        float2 f0 = upk2(acc[nn][0]);
        float2 f1 = upk2(acc[nn][1]);
        float r0 = f0.x + f0.y;
        float r1 = f1.x + f1.y;
        if (ch == 0) {
            g_p[node * 64 + lane] = __float2half_rn(r0);
            g_p[node * 64 + lane + 32] = __float2half_rn(r1);
        } else {
            g_r[node * 64 + lane] = r0;
            g_r[node * 64 + lane + 32] = r1;
        }
    }
}

// ---------------- gather2: agg2[n] = mean_{s in N(n)} p[s]  (p fp16) ----------------
__global__ void __launch_bounds__(256) gather2_kernel() {
    int gt = blockIdx.x * 256 + threadIdx.x;
    int n = gt >> 5;
    if (n >= N_NODES) return;
    int lane = gt & 31;
    int beg = __ldg(g_rowptr + n), end = __ldg(g_rowptr + n + 1);
    const unsigned* p2 = (const unsigned*)g_p;   // row stride 32 uints (2 halves each)

    float ax = 0.f, ay = 0.f;
#define ACC2(U) do { \
    float2 f = __half22float2(*(const __half2*)&(U)); \
    ax += f.x; ay += f.y; } while (0)
    int j = beg;
    for (; j + 7 < end; j += 8) {
        unsigned u0 = __ldg(p2 + __ldg(&g_nbr2[j].x)     * 32 + lane);
        unsigned u1 = __ldg(p2 + __ldg(&g_nbr2[j + 1].x) * 32 + lane);
        unsigned u2 = __ldg(p2 + __ldg(&g_nbr2[j + 2].x) * 32 + lane);
        unsigned u3 = __ldg(p2 + __ldg(&g_nbr2[j + 3].x) * 32 + lane);
        unsigned u4 = __ldg(p2 + __ldg(&g_nbr2[j + 4].x) * 32 + lane);
        unsigned u5 = __ldg(p2 + __ldg(&g_nbr2[j + 5].x) * 32 + lane);
        unsigned u6 = __ldg(p2 + __ldg(&g_nbr2[j + 6].x) * 32 + lane);
        unsigned u7 = __ldg(p2 + __ldg(&g_nbr2[j + 7].x) * 32 + lane);
        ACC2(u0); ACC2(u1); ACC2(u2); ACC2(u3);
        ACC2(u4); ACC2(u5); ACC2(u6); ACC2(u7);
    }
    for (; j + 3 < end; j += 4) {
        unsigned u0 = __ldg(p2 + __ldg(&g_nbr2[j].x)     * 32 + lane);
        unsigned u1 = __ldg(p2 + __ldg(&g_nbr2[j + 1].x) * 32 + lane);
        unsigned u2 = __ldg(p2 + __ldg(&g_nbr2[j + 2].x) * 32 + lane);
        unsigned u3 = __ldg(p2 + __ldg(&g_nbr2[j + 3].x) * 32 + lane);
        ACC2(u0); ACC2(u1); ACC2(u2); ACC2(u3);
    }
    for (; j < end; j++) {
        unsigned u0 = __ldg(p2 + __ldg(&g_nbr2[j].x) * 32 + lane);
        ACC2(u0);
    }
#undef ACC2
    float inv = 1.0f / fmaxf((float)(end - beg), 1.0f);
    ((float2*)g_agg2)[n * 32 + lane] = make_float2(ax * inv, ay * inv);
}

// ---------------- final: h2 = agg2 + b2 + r ; run-length segment-max -> omax --------
__global__ void __launch_bounds__(256) final_kernel(const float* __restrict__ b2,
                                                    const int* __restrict__ batch) {
    const int tid = threadIdx.x, lane = tid & 31, warp = tid >> 5;
    const int n0 = blockIdx.x * 128 + warp * 16;
    float2 bb = ((const float2*)b2)[lane];
    const float2* ag2 = (const float2*)g_agg2;
    const float2* r2 = (const float2*)g_r;

    int curb = -1;
    float mx = 0.f, my = 0.f;
#pragma unroll
    for (int t = 0; t < 16; t++) {
        int node = n0 + t;
        if (node >= N_NODES) break;
        float2 ag = ag2[node * 32 + lane];
        float2 rr = r2[node * 32 + lane];
        float vx = ag.x + rr.x + bb.x;
        float vy = ag.y + rr.y + bb.y;
        int b = batch[node];
        if (b != curb) {
            if (curb >= 0) {
                atomicMax(&g_omax[curb * 64 + lane * 2], ordf(mx));
                atomicMax(&g_omax[curb * 64 + lane * 2 + 1], ordf(my));
            }
            curb = b; mx = vx; my = vy;
        } else {
            mx = fmaxf(mx, vx);
            my = fmaxf(my, vy);
        }
    }
    if (curb >= 0) {
        atomicMax(&g_omax[curb * 64 + lane * 2], ordf(mx));
        atomicMax(&g_omax[curb * 64 + lane * 2 + 1], ordf(my));
    }
}

// ---------------- decode ordered uints into d_out ----------------
__global__ void out_kernel(float* __restrict__ out) {
    int i = blockIdx.x * 256 + threadIdx.x;
    if (i >= NGRAPH * D0) return;
    unsigned o = g_omax[i];
    out[i] = (o & 0x80000000u) ? __uint_as_float(o & 0x7FFFFFFFu)
                               : __uint_as_float(~o);
}

// ---------------- launch: fork-join graph with stream B -----------------------------
// Chunk layout: 4 node chunks aligned to 64-node dense2 tiles (391/391/391/390 tiles).
extern "C" void kernel_launch(void* const* d_in, const int* in_sizes, int n_in,
                              void* d_out, int out_size) {
    const int*   x     = (const int*)d_in[0];
    const int*   ei    = (const int*)d_in[1];     // [2, E]
    const int*   batch = (const int*)d_in[2];
    // d_in[3] = edge_attr (unused by SAGEConv)
    const float* embed = (const float*)d_in[4];
    const float* W1l   = (const float*)d_in[5];
    const float* b1    = (const float*)d_in[6];
    const float* W1r   = (const float*)d_in[7];
    const float* W2l   = (const float*)d_in[8];
    const float* b2    = (const float*)d_in[9];
    const float* W2r   = (const float*)d_in[10];
    float* out = (float*)d_out;

    const int* src = ei;
    const int* dst = ei + N_EDGES;

    cudaFuncSetAttribute(dense2_kernel,
                         cudaFuncAttributeMaxDynamicSharedMemorySize, 98304);

    static const int n_base[4]  = {0, 25024, 50048, 75072};
    static const int n_cnt[4]   = {25024, 25024, 25024, 24928};
    static const int t_base[4]  = {0, 391, 782, 1173};
    static const int t_cnt[4]   = {391, 391, 391, 390};

    cudaStream_t sB;
    cudaStreamCreateWithFlags(&sB, cudaStreamNonBlocking);
    cudaEvent_t evF, evQ, evG[4], evD;
    cudaEventCreateWithFlags(&evF, cudaEventDisableTiming);
    cudaEventCreateWithFlags(&evQ, cudaEventDisableTiming);
    for (int c = 0; c < 4; c++) cudaEventCreateWithFlags(&evG[c], cudaEventDisableTiming);
    cudaEventCreateWithFlags(&evD, cudaEventDisableTiming);

    // main stream head; fork stream B for the Q/R pre-GEMM
    zinit_kernel<<<512, 256>>>();
    cudaEventRecord(evF, 0);
    cudaStreamWaitEvent(sB, evF, 0);
    preqr_kernel<<<(VOCAB * D1 + 255) / 256, 256, 0, sB>>>(embed, W1l, W1r);
    cudaEventRecord(evQ, sB);

    // CSR chain on main (independent of Q/R)
    hist_kernel<<<(N_EDGES + 255) / 256, 256>>>(dst);
    scan1_kernel<<<SCAN_NB, 256>>>();
    scan2_kernel<<<1, 512>>>();
    scan3_kernel<<<SCAN_NB, 256>>>();
    fill_kernel<<<(N_EDGES + 255) / 256, 256>>>(src, dst, x);

    // join Q/R, then pipeline gather1h (main) with dense2 (stream B), 4 chunks
    cudaStreamWaitEvent(0, evQ, 0);
    for (int c = 0; c < 4; c++) {
        gather1h_kernel<<<(n_cnt[c] * 32 + 255) / 256, 256>>>(x, b1, n_base[c]);
        cudaEventRecord(evG[c], 0);
        cudaStreamWaitEvent(sB, evG[c], 0);
        dense2_kernel<<<t_cnt[c], 256, 98304, sB>>>(W2l, W2r, t_base[c]);
    }
    cudaEventRecord(evD, sB);
    cudaStreamWaitEvent(0, evD, 0);

    // tail on main
    gather2_kernel<<<(N_NODES * 32 + 255) / 256, 256>>>();
    final_kernel<<<(N_NODES + 127) / 128, 256>>>(b2, batch);
    out_kernel<<<(NGRAPH * D0 + 255) / 256, 256>>>(out);
}

// round 16
// speedup vs baseline: 1.0663x; 1.0663x over previous
#include <cuda_runtime.h>
#include <cuda_fp16.h>
#include <cstdint>

#define N_NODES 100000
#define N_EDGES 1600000
#define NGRAPH  512
#define VOCAB   10000
#define D0 64
#define D1 128
#define SCAN_NB 391   // ceil(N_NODES / 256)

// ---------------- scratch (device globals) ----------------
__device__ int g_cnt[N_NODES];
__device__ int g_rowptr[N_NODES + 1];
__device__ int g_cur[N_NODES];
__device__ int g_bsum[SCAN_NB];
__device__ int g_boff[SCAN_NB];
__device__ __align__(8) int2 g_nbr2[N_EDGES];        // {src node id, x[src]} per CSR slot

__device__ __align__(16) __half g_q[VOCAB * D1];     // embed @ W1l   (fp16, 2.56MB)
__device__ __align__(16) float  g_R[VOCAB * D1];     // embed @ W1r   (fp32, 5.12MB)
__device__ __align__(16) __half g_h1h[N_NODES * D1]; // relu layer1   (fp16, 25.6MB)
__device__ __align__(16) __half g_p[N_NODES * D0];   // h1 @ W2l      (fp16, 12.8MB)
__device__ __align__(16) float  g_r[N_NODES * D0];   // h1 @ W2r      (25.6MB)
__device__ __align__(16) float  g_agg2[N_NODES * D0];
__device__ unsigned g_omax[NGRAPH * D0];

// ordered-uint mapping: monotone in float value
__device__ __forceinline__ unsigned ordf(float f) {
    unsigned u = __float_as_uint(f);
    return (u & 0x80000000u) ? ~u : (u | 0x80000000u);
}
#define ORD_NEG_INIT 0x00800000u   // ordf(-FLT_MAX)

// ---------------- f32x2 packed math ----------------
__device__ __forceinline__ unsigned long long pk2(float x, float y) {
    unsigned long long r;
    asm("mov.b64 %0, {%1, %2};" : "=l"(r) : "f"(x), "f"(y));
    return r;
}
__device__ __forceinline__ float2 upk2(unsigned long long v) {
    float2 r;
    asm("mov.b64 {%0, %1}, %2;" : "=f"(r.x), "=f"(r.y) : "l"(v));
    return r;
}
__device__ __forceinline__ void ffma2(unsigned long long& d, unsigned long long a,
                                      unsigned long long b) {
    asm("fma.rn.f32x2 %0, %1, %2, %0;" : "+l"(d) : "l"(a), "l"(b));
}

// ---------------- zinit: zero counters, arm omax ----------------
__global__ void zinit_kernel() {
    int gid = blockIdx.x * 256 + threadIdx.x;
    int stride = gridDim.x * 256;
    for (int j = gid; j < N_NODES; j += stride) g_cnt[j] = 0;
    for (int j = gid; j < NGRAPH * D0; j += stride) g_omax[j] = ORD_NEG_INIT;
}

// ---------------- preQR: Q = embed@W1l (fp16), R = embed@W1r (fp32) [stream B] -----
__global__ void preqr_kernel(const float* __restrict__ embed,
                             const float* __restrict__ W1l,
                             const float* __restrict__ W1r) {
    int gid = blockIdx.x * 256 + threadIdx.x;
    if (gid >= VOCAB * D1) return;
    int v = gid >> 7, c = gid & 127;
    float q = 0.f, r = 0.f;
#pragma unroll 8
    for (int k = 0; k < 64; k++) {
        float e = __ldg(embed + v * 64 + k);
        q = fmaf(e, __ldg(W1l + k * 128 + c), q);
        r = fmaf(e, __ldg(W1r + k * 128 + c), r);
    }
    g_q[gid] = __float2half_rn(q);
    g_R[gid] = r;
}

// ---------------- histogram of dst ----------------
__global__ void hist_kernel(const int* __restrict__ dst) {
    int e = blockIdx.x * 256 + threadIdx.x;
    if (e < N_EDGES) atomicAdd(&g_cnt[dst[e]], 1);
}

// ---------------- scan step 1 ----------------
__global__ void scan1_kernel() {
    int b = blockIdx.x;
    int i = b * 256 + threadIdx.x;
    int v = (i < N_NODES) ? g_cnt[i] : 0;
#pragma unroll
    for (int o = 16; o; o >>= 1) v += __shfl_down_sync(0xFFFFFFFFu, v, o);
    __shared__ int ws[8];
    if ((threadIdx.x & 31) == 0) ws[threadIdx.x >> 5] = v;
    __syncthreads();
    if (threadIdx.x == 0) {
        int s = 0;
#pragma unroll
        for (int k = 0; k < 8; k++) s += ws[k];
        g_bsum[b] = s;
    }
}

// ---------------- scan step 2 ----------------
__global__ void scan2_kernel() {
    __shared__ int s[512];
    int t = threadIdx.x;
    int v = (t < SCAN_NB) ? g_bsum[t] : 0;
    s[t] = v;
    __syncthreads();
    for (int o = 1; o < 512; o <<= 1) {
        int u = (t >= o) ? s[t - o] : 0;
        __syncthreads();
        s[t] += u;
        __syncthreads();
    }
    if (t < SCAN_NB) g_boff[t] = s[t] - v;
    if (t == 0) g_rowptr[N_NODES] = N_EDGES;
}

// ---------------- scan step 3 ----------------
__global__ void scan3_kernel() {
    int b = blockIdx.x, t = threadIdx.x;
    int i = b * 256 + t;
    int v = (i < N_NODES) ? g_cnt[i] : 0;
    int lane = t & 31, w = t >> 5;
    int sc = v;
#pragma unroll
    for (int o = 1; o < 32; o <<= 1) {
        int u = __shfl_up_sync(0xFFFFFFFFu, sc, o);
        if (lane >= o) sc += u;
    }
    __shared__ int ws[8];
    if (lane == 31) ws[w] = sc;
    __syncthreads();
    if (t < 8) {
        int u = ws[t];
        int s2 = u;
#pragma unroll
        for (int o = 1; o < 8; o <<= 1) {
            int q = __shfl_up_sync(0xFFu, s2, o);
            if (t >= o) s2 += q;
        }
        ws[t] = s2 - u;
    }
    __syncthreads();
    int excl = sc - v + ws[w] + g_boff[b];
    if (i < N_NODES) {
        g_rowptr[i] = excl;
        g_cur[i] = excl;
    }
}

// ---------------- fill neighbor lists: single int2 {src, x[src]} store -------------
__global__ void fill_kernel(const int* __restrict__ src, const int* __restrict__ dst,
                            const int* __restrict__ x) {
    int e = blockIdx.x * 256 + threadIdx.x;
    if (e >= N_EDGES) return;
    int d = dst[e];
    int s = src[e];
    int xs = __ldg(x + s);
    int pos = atomicAdd(&g_cur[d], 1);
    g_nbr2[pos] = make_int2(s, xs);
}

// ---------------- gather1h: h1[n] = relu(mean Q[x[s]] + R[x[n]] + b1) --------------
// warp per node; lane covers 4 cols (uint2 = 4 halves). 8-edge unroll for MLP.
__global__ void __launch_bounds__(256) gather1h_kernel(const int* __restrict__ x,
                                                       const float* __restrict__ b1) {
    int gt = blockIdx.x * 256 + threadIdx.x;
    int n = gt >> 5;
    if (n >= N_NODES) return;
    int lane = gt & 31;
    int beg = __ldg(g_rowptr + n), end = __ldg(g_rowptr + n + 1);
    const uint2* q2 = (const uint2*)g_q;   // row stride 32 uint2

    float a0 = 0.f, a1 = 0.f, a2 = 0.f, a3 = 0.f;
#define ACC4(U) do { \
    float2 f0 = __half22float2(*(const __half2*)&(U).x); \
    float2 f1 = __half22float2(*(const __half2*)&(U).y); \
    a0 += f0.x; a1 += f0.y; a2 += f1.x; a3 += f1.y; } while (0)
    int j = beg;
    for (; j + 7 < end; j += 8) {
        uint2 u0 = __ldg(q2 + __ldg(&g_nbr2[j].y)     * 32 + lane);
        uint2 u1 = __ldg(q2 + __ldg(&g_nbr2[j + 1].y) * 32 + lane);
        uint2 u2 = __ldg(q2 + __ldg(&g_nbr2[j + 2].y) * 32 + lane);
        uint2 u3 = __ldg(q2 + __ldg(&g_nbr2[j + 3].y) * 32 + lane);
        uint2 u4 = __ldg(q2 + __ldg(&g_nbr2[j + 4].y) * 32 + lane);
        uint2 u5 = __ldg(q2 + __ldg(&g_nbr2[j + 5].y) * 32 + lane);
        uint2 u6 = __ldg(q2 + __ldg(&g_nbr2[j + 6].y) * 32 + lane);
        uint2 u7 = __ldg(q2 + __ldg(&g_nbr2[j + 7].y) * 32 + lane);
        ACC4(u0); ACC4(u1); ACC4(u2); ACC4(u3);
        ACC4(u4); ACC4(u5); ACC4(u6); ACC4(u7);
    }
    for (; j + 3 < end; j += 4) {
        uint2 u0 = __ldg(q2 + __ldg(&g_nbr2[j].y)     * 32 + lane);
        uint2 u1 = __ldg(q2 + __ldg(&g_nbr2[j + 1].y) * 32 + lane);
        uint2 u2 = __ldg(q2 + __ldg(&g_nbr2[j + 2].y) * 32 + lane);
        uint2 u3 = __ldg(q2 + __ldg(&g_nbr2[j + 3].y) * 32 + lane);
        ACC4(u0); ACC4(u1); ACC4(u2); ACC4(u3);
    }
    for (; j < end; j++) {
        uint2 u0 = __ldg(q2 + __ldg(&g_nbr2[j].y) * 32 + lane);
        ACC4(u0);
    }
#undef ACC4
    float inv = 1.0f / fmaxf((float)(end - beg), 1.0f);
    int xn = __ldg(x + n);
    float4 rv = __ldg(((const float4*)g_R) + xn * 32 + lane);
    float4 bv = __ldg(((const float4*)b1) + lane);
    __half2 h01 = __floats2half2_rn(fmaxf(fmaf(a0, inv, rv.x + bv.x), 0.f),
                                    fmaxf(fmaf(a1, inv, rv.y + bv.y), 0.f));
    __half2 h23 = __floats2half2_rn(fmaxf(fmaf(a2, inv, rv.z + bv.z), 0.f),
                                    fmaxf(fmaf(a3, inv, rv.w + bv.w), 0.f));
    uint2 o;
    o.x = *(const unsigned*)&h01;
    o.y = *(const unsigned*)&h23;
    ((uint2*)g_h1h)[n * 32 + lane] = o;
}

// ---------------- dense2: [p | r] = h1 @ [W2l | W2r]  via f32x2, 512 threads -------
// 512 thr = 16 warps, 64 nodes/block, smem 96KB (2 CTAs/SM -> 32 warps/SM).
// warp w: node group (w&7)*8 (8 nodes), col half (w>>3)*64.
__global__ void __launch_bounds__(512) dense2_kernel(const float* __restrict__ W2l,
                                                     const float* __restrict__ W2r) {
    extern __shared__ float sm[];
    float* sW = sm;            // 16384 floats: [(k>>1)*256 + c*2 + (k&1)]
    float* sH = sm + 16384;    // 8192 floats:  [(t>>1)*256 + (k>>1)*4 + (t&1)*2 + (k&1)]
    const int tid = threadIdx.x, lane = tid & 31, wid = tid >> 5;
    const int n0 = blockIdx.x * 64;

    for (int idx = tid; idx < 16384; idx += 512) {
        int k = idx >> 7, c = idx & 127;
        float v = (c < 64) ? __ldg(W2l + k * 64 + c) : __ldg(W2r + k * 64 + (c - 64));
        sW[((k >> 1) << 8) + (c << 1) + (k & 1)] = v;
    }
    // stage h1 tile from fp16: each idx covers (t, 4 consecutive k)
    for (int idx = tid; idx < 2048; idx += 512) {
        int t = idx >> 5, kq = idx & 31;     // kq: group of 4 k
        int n = n0 + t;
        uint2 u = (n < N_NODES) ? __ldg(((const uint2*)g_h1h) + n * 32 + kq)
                                : make_uint2(0u, 0u);
        float2 f0 = __half22float2(*(const __half2*)&u.x);
        float2 f1 = __half22float2(*(const __half2*)&u.y);
        float* dstp = sH + ((t >> 1) << 8) + (kq << 3) + ((t & 1) << 1);
        *(float2*)dstp = f0;
        *(float2*)(dstp + 4) = f1;
    }
    __syncthreads();

    const int ng = (wid & 7) * 8;       // node group base (8 nodes)
    const int ch = (wid >> 3) * 64;     // col half: 0 -> p, 64 -> r
    unsigned long long acc[8][2];
#pragma unroll
    for (int nn = 0; nn < 8; nn++) { acc[nn][0] = 0ull; acc[nn][1] = 0ull; }

    const float2* sW2 = (const float2*)sW;   // float2 idx = j2*128 + c
    const float4* sH4 = (const float4*)sH;   // float4 idx = (t>>1)*64 + j2

    for (int j2 = 0; j2 < 64; j2++) {
        float2 t0 = sW2[j2 * 128 + ch + lane];
        float2 t1 = sW2[j2 * 128 + ch + lane + 32];
        unsigned long long w0 = pk2(t0.x, t0.y);
        unsigned long long w1 = pk2(t1.x, t1.y);
#pragma unroll
        for (int p4 = 0; p4 < 4; p4++) {
            float4 hv = sH4[((ng >> 1) + p4) * 64 + j2];   // broadcast
            unsigned long long h0 = pk2(hv.x, hv.y);
            unsigned long long h1v = pk2(hv.z, hv.w);
            ffma2(acc[2 * p4][0], h0, w0);
            ffma2(acc[2 * p4][1], h0, w1);
            ffma2(acc[2 * p4 + 1][0], h1v, w0);
            ffma2(acc[2 * p4 + 1][1], h1v, w1);
        }
    }

#pragma unroll
    for (int nn = 0; nn < 8; nn++) {
        int node = n0 + ng + nn;
        if (node >= N_NODES) break;
        float2 f0 = upk2(acc[nn][0]);
        float2 f1 = upk2(acc[nn][1]);
        float r0 = f0.x + f0.y;
        float r1 = f1.x + f1.y;
        if (ch == 0) {
            g_p[node * 64 + lane] = __float2half_rn(r0);
            g_p[node * 64 + lane + 32] = __float2half_rn(r1);
        } else {
            g_r[node * 64 + lane] = r0;
            g_r[node * 64 + lane + 32] = r1;
        }
    }
}

// ---------------- gather2: agg2[n] = mean_{s in N(n)} p[s]  (p fp16) ----------------
__global__ void __launch_bounds__(256) gather2_kernel() {
    int gt = blockIdx.x * 256 + threadIdx.x;
    int n = gt >> 5;
    if (n >= N_NODES) return;
    int lane = gt & 31;
    int beg = __ldg(g_rowptr + n), end = __ldg(g_rowptr + n + 1);
    const unsigned* p2 = (const unsigned*)g_p;   // row stride 32 uints (2 halves each)

    float ax = 0.f, ay = 0.f;
#define ACC2(U) do { \
    float2 f = __half22float2(*(const __half2*)&(U)); \
    ax += f.x; ay += f.y; } while (0)
    int j = beg;
    for (; j + 7 < end; j += 8) {
        unsigned u0 = __ldg(p2 + __ldg(&g_nbr2[j].x)     * 32 + lane);
        unsigned u1 = __ldg(p2 + __ldg(&g_nbr2[j + 1].x) * 32 + lane);
        unsigned u2 = __ldg(p2 + __ldg(&g_nbr2[j + 2].x) * 32 + lane);
        unsigned u3 = __ldg(p2 + __ldg(&g_nbr2[j + 3].x) * 32 + lane);
        unsigned u4 = __ldg(p2 + __ldg(&g_nbr2[j + 4].x) * 32 + lane);
        unsigned u5 = __ldg(p2 + __ldg(&g_nbr2[j + 5].x) * 32 + lane);
        unsigned u6 = __ldg(p2 + __ldg(&g_nbr2[j + 6].x) * 32 + lane);
        unsigned u7 = __ldg(p2 + __ldg(&g_nbr2[j + 7].x) * 32 + lane);
        ACC2(u0); ACC2(u1); ACC2(u2); ACC2(u3);
        ACC2(u4); ACC2(u5); ACC2(u6); ACC2(u7);
    }
    for (; j + 3 < end; j += 4) {
        unsigned u0 = __ldg(p2 + __ldg(&g_nbr2[j].x)     * 32 + lane);
        unsigned u1 = __ldg(p2 + __ldg(&g_nbr2[j + 1].x) * 32 + lane);
        unsigned u2 = __ldg(p2 + __ldg(&g_nbr2[j + 2].x) * 32 + lane);
        unsigned u3 = __ldg(p2 + __ldg(&g_nbr2[j + 3].x) * 32 + lane);
        ACC2(u0); ACC2(u1); ACC2(u2); ACC2(u3);
    }
    for (; j < end; j++) {
        unsigned u0 = __ldg(p2 + __ldg(&g_nbr2[j].x) * 32 + lane);
        ACC2(u0);
    }
#undef ACC2
    float inv = 1.0f / fmaxf((float)(end - beg), 1.0f);
    ((float2*)g_agg2)[n * 32 + lane] = make_float2(ax * inv, ay * inv);
}

// ---------------- final: h2 = agg2 + b2 + r ; run-length segment-max -> omax --------
__global__ void __launch_bounds__(256) final_kernel(const float* __restrict__ b2,
                                                    const int* __restrict__ batch) {
    const int tid = threadIdx.x, lane = tid & 31, warp = tid >> 5;
    const int n0 = blockIdx.x * 128 + warp * 16;
    float2 bb = ((const float2*)b2)[lane];
    const float2* ag2 = (const float2*)g_agg2;
    const float2* r2 = (const float2*)g_r;

    int curb = -1;
    float mx = 0.f, my = 0.f;
#pragma unroll
    for (int t = 0; t < 16; t++) {
        int node = n0 + t;
        if (node >= N_NODES) break;
        float2 ag = ag2[node * 32 + lane];
        float2 rr = r2[node * 32 + lane];
        float vx = ag.x + rr.x + bb.x;
        float vy = ag.y + rr.y + bb.y;
        int b = batch[node];
        if (b != curb) {
            if (curb >= 0) {
                atomicMax(&g_omax[curb * 64 + lane * 2], ordf(mx));
                atomicMax(&g_omax[curb * 64 + lane * 2 + 1], ordf(my));
            }
            curb = b; mx = vx; my = vy;
        } else {
            mx = fmaxf(mx, vx);
            my = fmaxf(my, vy);
        }
    }
    if (curb >= 0) {
        atomicMax(&g_omax[curb * 64 + lane * 2], ordf(mx));
        atomicMax(&g_omax[curb * 64 + lane * 2 + 1], ordf(my));
    }
}

// ---------------- decode ordered uints into d_out ----------------
__global__ void out_kernel(float* __restrict__ out) {
    int i = blockIdx.x * 256 + threadIdx.x;
    if (i >= NGRAPH * D0) return;
    unsigned o = g_omax[i];
    out[i] = (o & 0x80000000u) ? __uint_as_float(o & 0x7FFFFFFFu)
                               : __uint_as_float(~o);
}

// ---------------- launch: preQR forked onto stream B; rest serial on main ----------
extern "C" void kernel_launch(void* const* d_in, const int* in_sizes, int n_in,
                              void* d_out, int out_size) {
    const int*   x     = (const int*)d_in[0];
    const int*   ei    = (const int*)d_in[1];     // [2, E]
    const int*   batch = (const int*)d_in[2];
    // d_in[3] = edge_attr (unused by SAGEConv)
    const float* embed = (const float*)d_in[4];
    const float* W1l   = (const float*)d_in[5];
    const float* b1    = (const float*)d_in[6];
    const float* W1r   = (const float*)d_in[7];
    const float* W2l   = (const float*)d_in[8];
    const float* b2    = (const float*)d_in[9];
    const float* W2r   = (const float*)d_in[10];
    float* out = (float*)d_out;

    const int* src = ei;
    const int* dst = ei + N_EDGES;

    cudaFuncSetAttribute(dense2_kernel,
                         cudaFuncAttributeMaxDynamicSharedMemorySize, 98304);

    cudaStream_t sB;
    cudaStreamCreateWithFlags(&sB, cudaStreamNonBlocking);
    cudaEvent_t evF, evQ;
    cudaEventCreateWithFlags(&evF, cudaEventDisableTiming);
    cudaEventCreateWithFlags(&evQ, cudaEventDisableTiming);

    // fork: preQR (writes g_q/g_R only) runs concurrently with the CSR chain
    zinit_kernel<<<512, 256>>>();
    cudaEventRecord(evF, 0);
    cudaStreamWaitEvent(sB, evF, 0);
    preqr_kernel<<<(VOCAB * D1 + 255) / 256, 256, 0, sB>>>(embed, W1l, W1r);
    cudaEventRecord(evQ, sB);

    hist_kernel<<<(N_EDGES + 255) / 256, 256>>>(dst);
    scan1_kernel<<<SCAN_NB, 256>>>();
    scan2_kernel<<<1, 512>>>();
    scan3_kernel<<<SCAN_NB, 256>>>();
    fill_kernel<<<(N_EDGES + 255) / 256, 256>>>(src, dst, x);

    // join before gather1h consumes g_q/g_R
    cudaStreamWaitEvent(0, evQ, 0);
    gather1h_kernel<<<(N_NODES * 32 + 255) / 256, 256>>>(x, b1);
    dense2_kernel<<<(N_NODES + 63) / 64, 512, 98304>>>(W2l, W2r);
    gather2_kernel<<<(N_NODES * 32 + 255) / 256, 256>>>();
    final_kernel<<<(N_NODES + 127) / 128, 256>>>(b2, batch);
    out_kernel<<<(NGRAPH * D0 + 255) / 256, 256>>>(out);
}